// round 12
// baseline (speedup 1.0000x reference)
#include <cuda_runtime.h>
#include <math.h>

#define K 9
#define TPB 128
#define WARPS (TPB / 32)
#define GRID 2048
#define RPT 4
#define WT_ROWS 128                  // rows per warp-tile (32 lanes * RPT)
#define WT_F   (WT_ROWS * K)         // 1152 floats
#define WT_F4  (WT_F / 4)            // 288 float4

#define ALPHA       0.4f
#define W_FAR       7.0f
#define DELTA_FAR   0.15f
#define W_TAIL      9.0f
#define W_LPEAK     12.0f
#define PROB_MARGIN 0.35f
#define W_EMD       1.2f
#define INV_LOGK    0.45511961331341866f   // 1/ln(9)
#define LOG2E       1.4426950408889634f
#define LN2         0.6931471805599453f

__device__ double g_partials[GRID];
__device__ unsigned int g_count = 0;

__device__ __forceinline__ unsigned smem_u32(const void* p) {
    return (unsigned)__cvta_generic_to_shared(p);
}
__device__ __forceinline__ void cp_async16(unsigned dst, const void* src) {
    asm volatile("cp.async.cg.shared.global [%0], [%1], 16;" :: "r"(dst), "l"(src));
}
__device__ __forceinline__ void cp_async4(unsigned dst, const void* src) {
    asm volatile("cp.async.ca.shared.global [%0], [%1], 4;" :: "r"(dst), "l"(src));
}
#define CP_COMMIT() asm volatile("cp.async.commit_group;")
#define CP_WAIT1()  asm volatile("cp.async.wait_group 1;" ::: "memory")

__global__ void __launch_bounds__(TPB)
ordinal_loss_fused(const float* __restrict__ logits,
                   const int*   __restrict__ y,
                   float* __restrict__ out,
                   int n, double inv_n)
{
    __shared__ __align__(16) float sx[WARPS][2][WT_F];    // 36 KB (fits 6 blocks/SM)
    __shared__ float2 s_t2[81];
    __shared__ float wsum[WARPS];
    __shared__ int   s_last;

    const int lane = threadIdx.x & 31;
    const int wid  = threadIdx.x >> 5;

    if (threadIdx.x < 81) {
        const int yy = threadIdx.x / K;
        const int k  = threadIdx.x % K;
        const int d  = (k > yy) ? (k - yy) : (yy - k);
        const float dm1 = (float)(d - 1);
        s_t2[threadIdx.x] = make_float2((d > 1) ? dm1 * dm1 * dm1 : 0.f,
                                        (k <= yy) ? 1.f : 0.f);
    }

    const int ntiles = (n + WT_ROWS - 1) / WT_ROWS;       // 32768 for n=4.19M
    const int NW = GRID * WARPS;                          // 8192 warps total
    const int gw = blockIdx.x * WARPS + wid;

    // stage logits only (labels live in registers now)
    auto stage = [&](int buf, int tile) {
        const int row0 = tile * WT_ROWS;
        const int rows = min(WT_ROWS, n - row0);
        const unsigned bx = smem_u32(&sx[wid][buf][0]);
        if (rows == WT_ROWS) {
            const float4* s4 = reinterpret_cast<const float4*>(logits + (size_t)row0 * K);
            #pragma unroll
            for (int i = 0; i < 9; ++i) {
                const int idx = lane + i * 32;
                cp_async16(bx + idx * 16, s4 + idx);
            }
        } else if (rows > 0) {
            const float* src = logits + (size_t)row0 * K;
            for (int i = lane; i < rows * K; i += 32) cp_async4(bx + i * 4, src + i);
        }
    };

    // label fetch for a tile -> registers (coalesced int4 LDG)
    auto load_y = [&](int tile) -> int4 {
        int4 v = make_int4(0, 0, 0, 0);
        const int row0 = tile * WT_ROWS + lane * RPT;
        if (row0 + RPT <= n) {
            v = __ldg(reinterpret_cast<const int4*>(y) + (size_t)tile * 32 + lane);
        } else {
            if (row0 + 0 < n) v.x = y[row0 + 0];
            if (row0 + 1 < n) v.y = y[row0 + 1];
            if (row0 + 2 < n) v.z = y[row0 + 2];
            if (row0 + 3 < n) v.w = y[row0 + 3];
        }
        return v;
    };

    float acc = 0.f;
    int tile = gw;
    int cur = 0;

    int4 ycur = make_int4(0, 0, 0, 0);
    if (tile < ntiles) { stage(0, tile); ycur = load_y(tile); }
    CP_COMMIT();
    __syncthreads();          // covers s_t2 init; only pre-loop barrier

    for (; tile < ntiles; tile += NW) {
        const int nxt = tile + NW;
        int4 ynext = make_int4(0, 0, 0, 0);
        if (nxt < ntiles) { stage(cur ^ 1, nxt); ynext = load_y(nxt); }
        CP_COMMIT();
        CP_WAIT1();           // this warp's tile-cur group has landed
        __syncwarp();

        // this thread's 4 rows: 144 B at offset 144*lane (16B-aligned)
        float4 xq[9];
        const float4* xsrc = reinterpret_cast<const float4*>(&sx[wid][cur][lane * (RPT * K)]);
        #pragma unroll
        for (int i = 0; i < 9; ++i) xq[i] = xsrc[i];
        const float* xf = reinterpret_cast<const float*>(xq);

        const int row0g = tile * WT_ROWS + lane * RPT;
        const bool full = (row0g + RPT <= n);

        #pragma unroll
        for (int r = 0; r < RPT; ++r) {
            if (full || (row0g + r < n)) {
                const int yy = (r == 0) ? ycur.x : (r == 1) ? ycur.y : (r == 2) ? ycur.z : ycur.w;
                const float* xr = xf + r * K;

                float e[K];
                float s = 0.f;
                #pragma unroll
                for (int k = 0; k < K; ++k) {
                    e[k] = exp2f(xr[k] * LOG2E);
                    s += e[k];
                }
                const float inv = __frcp_rn(s);

                const float* xs = &sx[wid][cur][(lane * RPT + r) * K];
                const float xy = xs[yy];
                const int yl  = (yy > 0) ? yy - 1 : 0;
                const int yr2 = (yy < K - 1) ? yy + 1 : K - 1;
                const float eyE = exp2f(xy * LOG2E);
                float elE = exp2f(xs[yl]  * LOG2E);
                float erE = exp2f(xs[yr2] * LOG2E);
                elE = (yy > 0) ? elE : 0.f;
                erE = (yy < K - 1) ? erE : 0.f;

                const float nll = fmaf(__log2f(s), LN2, -xy);

                const float* t2 = reinterpret_cast<const float*>(&s_t2[yy * K]);
                const float cw[K] = {3.f/95.f, 7.f/95.f, 10.f/95.f, 10.f/95.f, 10.f/95.f,
                                     10.f/95.f, 10.f/95.f, 10.f/95.f, 25.f/95.f};
                float tailE = 0.f, farE = 0.f, c = 0.f, emdE = 0.f;
                #pragma unroll
                for (int k = 0; k < K; ++k) {
                    const float twk = t2[2 * k];
                    const float ttk = t2[2 * k + 1];
                    tailE = fmaf(twk, e[k], tailE);
                    if (twk > 0.f) farE = fmaxf(farE, e[k]);
                    c += e[k];
                    const float v = fmaf(ttk, -s, c);   // c - t*s
                    emdE = fmaf(v * v, cw[k], emdE);
                }

                const float rAf = fmaxf(fmaf(DELTA_FAR,   s, farE - eyE), 0.f);
                const float nmx = fmaxf(elE, erE);
                const float rAl = fmaxf(fmaf(PROB_MARGIN, s, nmx - eyE), 0.f);

                float ord = fmaf(W_FAR, rAf, W_TAIL * tailE);
                ord = fmaf(W_LPEAK, rAl, ord);
                ord = fmaf(W_EMD * emdE, inv, ord);     // emd carries inv^2 total
                acc += fmaf(nll, INV_LOGK, (ALPHA * inv) * ord);
            }
        }
        __syncwarp();          // lanes done reading before next stage overwrites
        cur ^= 1;
        ycur = ynext;
    }

    // deterministic block reduction
    #pragma unroll
    for (int o = 16; o > 0; o >>= 1)
        acc += __shfl_down_sync(0xffffffffu, acc, o);
    if (lane == 0) wsum[wid] = acc;
    __syncthreads();
    if (threadIdx.x == 0) {
        float b = 0.f;
        #pragma unroll
        for (int w = 0; w < WARPS; ++w) b += wsum[w];
        g_partials[blockIdx.x] = (double)b;
        __threadfence();
        const unsigned old = atomicAdd(&g_count, 1u);
        s_last = (old == GRID - 1) ? 1 : 0;
    }
    __syncthreads();

    // last block performs the deterministic, fixed-order final sum
    if (s_last) {
        __shared__ double dsum[WARPS];
        double sd = 0.0;
        #pragma unroll
        for (int i = 0; i < GRID / TPB; ++i)
            sd += g_partials[threadIdx.x + i * TPB];
        #pragma unroll
        for (int o = 16; o > 0; o >>= 1)
            sd += __shfl_down_sync(0xffffffffu, sd, o);
        if (lane == 0) dsum[wid] = sd;
        __syncthreads();
        if (threadIdx.x == 0) {
            double t = 0.0;
            #pragma unroll
            for (int w = 0; w < WARPS; ++w) t += dsum[w];
            out[0] = (float)(t * inv_n);
            g_count = 0;   // reset for next graph replay
        }
    }
}

extern "C" void kernel_launch(void* const* d_in, const int* in_sizes, int n_in,
                              void* d_out, int out_size)
{
    const float* logits = (const float*)d_in[0];
    const int*   yv     = (const int*)d_in[1];
    const int n = (n_in >= 2) ? in_sizes[1] : in_sizes[0] / K;

    ordinal_loss_fused<<<GRID, TPB>>>(logits, yv, (float*)d_out,
                                      n, 1.0 / (double)n);
}

// round 13
// speedup vs baseline: 1.0008x; 1.0008x over previous
#include <cuda_runtime.h>
#include <math.h>

#define K 9
#define TPB 128
#define WARPS (TPB / 32)
#define GRID 2048
#define RPT 4
#define WT_ROWS 128                  // rows per warp-tile (32 lanes * RPT)
#define WT_F   (WT_ROWS * K)         // 1152 floats
#define WT_F4  (WT_F / 4)            // 288 float4

#define ALPHA       0.4f
#define W_FAR       7.0f
#define DELTA_FAR   0.15f
#define W_TAIL      9.0f
#define W_LPEAK     12.0f
#define PROB_MARGIN 0.35f
#define W_EMD       1.2f
#define INV_LOGK    0.45511961331341866f   // 1/ln(9)
#define LOG2E       1.4426950408889634f
#define LN2         0.6931471805599453f

__device__ double g_partials[GRID];
__device__ unsigned int g_count = 0;

__device__ __forceinline__ unsigned smem_u32(const void* p) {
    return (unsigned)__cvta_generic_to_shared(p);
}
__device__ __forceinline__ void cp_async16(unsigned dst, const void* src) {
    asm volatile("cp.async.cg.shared.global [%0], [%1], 16;" :: "r"(dst), "l"(src));
}
__device__ __forceinline__ void cp_async4(unsigned dst, const void* src) {
    asm volatile("cp.async.ca.shared.global [%0], [%1], 4;" :: "r"(dst), "l"(src));
}
#define CP_COMMIT() asm volatile("cp.async.commit_group;")
#define CP_WAIT1()  asm volatile("cp.async.wait_group 1;" ::: "memory")

__global__ void __launch_bounds__(TPB)
ordinal_loss_fused(const float* __restrict__ logits,
                   const int*   __restrict__ y,
                   float* __restrict__ out,
                   int n, double inv_n)
{
    __shared__ __align__(16) float sx[WARPS][2][WT_F];    // 36 KB
    __shared__ __align__(16) int   sy[WARPS][2][WT_ROWS]; // 4 KB
    __shared__ float2 s_t2[81];
    __shared__ float wsum[WARPS];
    __shared__ int   s_last;

    const int lane = threadIdx.x & 31;
    const int wid  = threadIdx.x >> 5;

    if (threadIdx.x < 81) {
        const int yy = threadIdx.x / K;
        const int k  = threadIdx.x % K;
        const int d  = (k > yy) ? (k - yy) : (yy - k);
        const float dm1 = (float)(d - 1);
        s_t2[threadIdx.x] = make_float2((d > 1) ? dm1 * dm1 * dm1 : 0.f,
                                        (k <= yy) ? 1.f : 0.f);
    }

    const int ntiles = (n + WT_ROWS - 1) / WT_ROWS;       // 32768 for n=4.19M
    const int NW = GRID * WARPS;                          // 8192 warps
    const int gw = blockIdx.x * WARPS + wid;

    auto stage = [&](int buf, int tile) {
        const int row0 = tile * WT_ROWS;
        const int rows = min(WT_ROWS, n - row0);
        const unsigned bx = smem_u32(&sx[wid][buf][0]);
        const unsigned by = smem_u32(&sy[wid][buf][0]);
        if (rows == WT_ROWS) {
            const float4* s4 = reinterpret_cast<const float4*>(logits + (size_t)row0 * K);
            #pragma unroll
            for (int i = 0; i < 9; ++i) {
                const int idx = lane + i * 32;
                cp_async16(bx + idx * 16, s4 + idx);
            }
            cp_async16(by + lane * 16,
                       reinterpret_cast<const int4*>(y + row0) + lane);
        } else if (rows > 0) {
            const float* src = logits + (size_t)row0 * K;
            for (int i = lane; i < rows * K; i += 32) cp_async4(bx + i * 4, src + i);
            for (int i = lane; i < rows; i += 32)     cp_async4(by + i * 4, y + row0 + i);
            for (int i = rows + lane; i < WT_ROWS; i += 32) sy[wid][buf][i] = 0;
        }
    };

    float acc = 0.f;
    int tile = gw;
    int cur = 0;

    if (tile < ntiles) stage(0, tile);
    CP_COMMIT();
    __syncthreads();          // covers s_t2 init; only pre-loop barrier

    for (; tile < ntiles; tile += NW) {
        const int nxt = tile + NW;
        if (nxt < ntiles) stage(cur ^ 1, nxt);
        CP_COMMIT();
        CP_WAIT1();
        __syncwarp();

        // this thread's 4 rows: 144 B at offset 144*lane (16B-aligned)
        float4 xq[9];
        const float4* xsrc = reinterpret_cast<const float4*>(&sx[wid][cur][lane * (RPT * K)]);
        #pragma unroll
        for (int i = 0; i < 9; ++i) xq[i] = xsrc[i];
        const int4 y4 = *reinterpret_cast<const int4*>(&sy[wid][cur][lane * RPT]);
        const float* xf = reinterpret_cast<const float*>(xq);

        const int row0g = tile * WT_ROWS + lane * RPT;

        #pragma unroll
        for (int r = 0; r < RPT; ++r) {
            if (row0g + r < n) {
                const int yy = (r == 0) ? y4.x : (r == 1) ? y4.y : (r == 2) ? y4.z : y4.w;
                const float* xr = xf + r * K;

                float e[K];
                float s = 0.f;
                #pragma unroll
                for (int k = 0; k < K; ++k) {
                    e[k] = exp2f(xr[k] * LOG2E);
                    s += e[k];
                }
                const float inv = __frcp_rn(s);

                float* xs = &sx[wid][cur][(lane * RPT + r) * K];

                // read true-class logit BEFORE overwriting the row with e
                const float xy = xs[yy];
                const float nll = fmaf(__log2f(s), LN2, -xy);

                // overwrite this row's x slot with e (thread-private 36 B).
                // row base byte offset = 144*lane + 36*r: 8-aligned iff r even.
                if ((r & 1) == 0) {
                    float2* p2 = reinterpret_cast<float2*>(xs);
                    p2[0] = make_float2(e[0], e[1]);
                    p2[1] = make_float2(e[2], e[3]);
                    p2[2] = make_float2(e[4], e[5]);
                    p2[3] = make_float2(e[6], e[7]);
                    xs[8] = e[8];
                } else {
                    xs[0] = e[0];
                    float2* p2 = reinterpret_cast<float2*>(xs + 1);
                    p2[0] = make_float2(e[1], e[2]);
                    p2[1] = make_float2(e[3], e[4]);
                    p2[2] = make_float2(e[5], e[6]);
                    p2[3] = make_float2(e[7], e[8]);
                }

                // picks read e directly from smem: no extra exponentials
                const int yl  = (yy > 0) ? yy - 1 : 0;
                const int yr2 = (yy < K - 1) ? yy + 1 : K - 1;
                const float eyE = xs[yy];
                float elE = xs[yl];
                float erE = xs[yr2];
                elE = (yy > 0) ? elE : 0.f;
                erE = (yy < K - 1) ? erE : 0.f;

                const float* t2 = reinterpret_cast<const float*>(&s_t2[yy * K]);
                const float cw[K] = {3.f/95.f, 7.f/95.f, 10.f/95.f, 10.f/95.f, 10.f/95.f,
                                     10.f/95.f, 10.f/95.f, 10.f/95.f, 25.f/95.f};
                float tailE = 0.f, farE = 0.f, c = 0.f, emdE = 0.f;
                #pragma unroll
                for (int k = 0; k < K; ++k) {
                    const float twk = t2[2 * k];
                    const float ttk = t2[2 * k + 1];
                    tailE = fmaf(twk, e[k], tailE);
                    if (twk > 0.f) farE = fmaxf(farE, e[k]);
                    c += e[k];
                    const float v = fmaf(ttk, -s, c);   // c - t*s
                    emdE = fmaf(v * v, cw[k], emdE);
                }

                const float rAf = fmaxf(fmaf(DELTA_FAR,   s, farE - eyE), 0.f);
                const float nmx = fmaxf(elE, erE);
                const float rAl = fmaxf(fmaf(PROB_MARGIN, s, nmx - eyE), 0.f);

                float ord = fmaf(W_FAR, rAf, W_TAIL * tailE);
                ord = fmaf(W_LPEAK, rAl, ord);
                ord = fmaf(W_EMD * emdE, inv, ord);     // emd carries inv^2 total
                acc += fmaf(nll, INV_LOGK, (ALPHA * inv) * ord);
            }
        }
        __syncwarp();          // lanes done before next stage overwrites buffer
        cur ^= 1;
    }

    // deterministic block reduction
    #pragma unroll
    for (int o = 16; o > 0; o >>= 1)
        acc += __shfl_down_sync(0xffffffffu, acc, o);
    if (lane == 0) wsum[wid] = acc;
    __syncthreads();
    if (threadIdx.x == 0) {
        float b = 0.f;
        #pragma unroll
        for (int w = 0; w < WARPS; ++w) b += wsum[w];
        g_partials[blockIdx.x] = (double)b;
        __threadfence();
        const unsigned old = atomicAdd(&g_count, 1u);
        s_last = (old == GRID - 1) ? 1 : 0;
    }
    __syncthreads();

    // last block performs the deterministic, fixed-order final sum
    if (s_last) {
        __shared__ double dsum[WARPS];
        double sd = 0.0;
        #pragma unroll
        for (int i = 0; i < GRID / TPB; ++i)
            sd += g_partials[threadIdx.x + i * TPB];
        #pragma unroll
        for (int o = 16; o > 0; o >>= 1)
            sd += __shfl_down_sync(0xffffffffu, sd, o);
        if (lane == 0) dsum[wid] = sd;
        __syncthreads();
        if (threadIdx.x == 0) {
            double t = 0.0;
            #pragma unroll
            for (int w = 0; w < WARPS; ++w) t += dsum[w];
            out[0] = (float)(t * inv_n);
            g_count = 0;   // reset for next graph replay
        }
    }
}

extern "C" void kernel_launch(void* const* d_in, const int* in_sizes, int n_in,
                              void* d_out, int out_size)
{
    const float* logits = (const float*)d_in[0];
    const int*   yv     = (const int*)d_in[1];
    const int n = (n_in >= 2) ? in_sizes[1] : in_sizes[0] / K;

    ordinal_loss_fused<<<GRID, TPB>>>(logits, yv, (float*)d_out,
                                      n, 1.0 / (double)n);
}

// round 14
// speedup vs baseline: 1.1750x; 1.1741x over previous
#include <cuda_runtime.h>
#include <math.h>

#define K 9
#define TPB 128
#define WARPS (TPB / 32)
#define GRID 2048
#define RPT 4
#define WT_ROWS 128                  // rows per warp-tile (32 lanes * RPT)
#define WT_F   (WT_ROWS * K)         // 1152 floats
#define WT_F4  (WT_F / 4)            // 288 float4

#define ALPHA       0.4f
#define W_FAR       7.0f
#define DELTA_FAR   0.15f
#define W_TAIL      9.0f
#define W_LPEAK     12.0f
#define PROB_MARGIN 0.35f
#define W_EMD       1.2f
#define INV_LOGK    0.45511961331341866f   // 1/ln(9)
#define LOG2E       1.4426950408889634f
#define LN2         0.6931471805599453f

__device__ double g_partials[GRID];
__device__ unsigned int g_count = 0;

// ---- guaranteed single-instruction MUFU ops (independent of fast-math flags) ----
__device__ __forceinline__ float ex2_approx(float x) {
    float r;
    asm("ex2.approx.ftz.f32 %0, %1;" : "=f"(r) : "f"(x));
    return r;
}
__device__ __forceinline__ float lg2_approx(float x) {
    float r;
    asm("lg2.approx.ftz.f32 %0, %1;" : "=f"(r) : "f"(x));
    return r;
}
__device__ __forceinline__ float rcp_approx(float x) {
    float r;
    asm("rcp.approx.ftz.f32 %0, %1;" : "=f"(r) : "f"(x));
    return r;
}

__device__ __forceinline__ unsigned smem_u32(const void* p) {
    return (unsigned)__cvta_generic_to_shared(p);
}
__device__ __forceinline__ void cp_async16(unsigned dst, const void* src) {
    asm volatile("cp.async.cg.shared.global [%0], [%1], 16;" :: "r"(dst), "l"(src));
}
__device__ __forceinline__ void cp_async4(unsigned dst, const void* src) {
    asm volatile("cp.async.ca.shared.global [%0], [%1], 4;" :: "r"(dst), "l"(src));
}
#define CP_COMMIT() asm volatile("cp.async.commit_group;")
#define CP_WAIT1()  asm volatile("cp.async.wait_group 1;" ::: "memory")

__global__ void __launch_bounds__(TPB)
ordinal_loss_fused(const float* __restrict__ logits,
                   const int*   __restrict__ y,
                   float* __restrict__ out,
                   int n, double inv_n)
{
    __shared__ __align__(16) float sx[WARPS][2][WT_F];    // 36 KB
    __shared__ __align__(16) int   sy[WARPS][2][WT_ROWS]; // 4 KB
    __shared__ float2 s_t2[81];
    __shared__ float wsum[WARPS];
    __shared__ int   s_last;

    const int lane = threadIdx.x & 31;
    const int wid  = threadIdx.x >> 5;

    if (threadIdx.x < 81) {
        const int yy = threadIdx.x / K;
        const int k  = threadIdx.x % K;
        const int d  = (k > yy) ? (k - yy) : (yy - k);
        const float dm1 = (float)(d - 1);
        s_t2[threadIdx.x] = make_float2((d > 1) ? dm1 * dm1 * dm1 : 0.f,
                                        (k <= yy) ? 1.f : 0.f);
    }

    const int ntiles = (n + WT_ROWS - 1) / WT_ROWS;       // 32768 for n=4.19M
    const int NW = GRID * WARPS;                          // 8192 warps
    const int gw = blockIdx.x * WARPS + wid;

    auto stage = [&](int buf, int tile) {
        const int row0 = tile * WT_ROWS;
        const int rows = min(WT_ROWS, n - row0);
        const unsigned bx = smem_u32(&sx[wid][buf][0]);
        const unsigned by = smem_u32(&sy[wid][buf][0]);
        if (rows == WT_ROWS) {
            const float4* s4 = reinterpret_cast<const float4*>(logits + (size_t)row0 * K);
            #pragma unroll
            for (int i = 0; i < 9; ++i) {
                const int idx = lane + i * 32;
                cp_async16(bx + idx * 16, s4 + idx);
            }
            cp_async16(by + lane * 16,
                       reinterpret_cast<const int4*>(y + row0) + lane);
        } else if (rows > 0) {
            const float* src = logits + (size_t)row0 * K;
            for (int i = lane; i < rows * K; i += 32) cp_async4(bx + i * 4, src + i);
            for (int i = lane; i < rows; i += 32)     cp_async4(by + i * 4, y + row0 + i);
            for (int i = rows + lane; i < WT_ROWS; i += 32) sy[wid][buf][i] = 0;
        }
    };

    float acc = 0.f;
    int tile = gw;
    int cur = 0;

    if (tile < ntiles) stage(0, tile);
    CP_COMMIT();
    __syncthreads();          // covers s_t2 init; only pre-loop barrier

    for (; tile < ntiles; tile += NW) {
        const int nxt = tile + NW;
        if (nxt < ntiles) stage(cur ^ 1, nxt);
        CP_COMMIT();
        CP_WAIT1();
        __syncwarp();

        // this thread's 4 rows: 144 B at offset 144*lane (16B-aligned)
        float4 xq[9];
        const float4* xsrc = reinterpret_cast<const float4*>(&sx[wid][cur][lane * (RPT * K)]);
        #pragma unroll
        for (int i = 0; i < 9; ++i) xq[i] = xsrc[i];
        const int4 y4 = *reinterpret_cast<const int4*>(&sy[wid][cur][lane * RPT]);
        const float* xf = reinterpret_cast<const float*>(xq);

        const int row0g = tile * WT_ROWS + lane * RPT;

        #pragma unroll
        for (int r = 0; r < RPT; ++r) {
            if (row0g + r < n) {
                const int yy = (r == 0) ? y4.x : (r == 1) ? y4.y : (r == 2) ? y4.z : y4.w;
                const float* xr = xf + r * K;

                float e[K];
                float s = 0.f;
                #pragma unroll
                for (int k = 0; k < K; ++k) {
                    e[k] = ex2_approx(xr[k] * LOG2E);
                    s += e[k];
                }
                const float inv = rcp_approx(s);

                const float* xs = &sx[wid][cur][(lane * RPT + r) * K];
                const float xy = xs[yy];
                const int yl  = (yy > 0) ? yy - 1 : 0;
                const int yr2 = (yy < K - 1) ? yy + 1 : K - 1;
                const float eyE = ex2_approx(xy * LOG2E);
                float elE = ex2_approx(xs[yl]  * LOG2E);
                float erE = ex2_approx(xs[yr2] * LOG2E);
                elE = (yy > 0) ? elE : 0.f;
                erE = (yy < K - 1) ? erE : 0.f;

                const float nll = fmaf(lg2_approx(s), LN2, -xy);

                const float* t2 = reinterpret_cast<const float*>(&s_t2[yy * K]);
                const float cw[K] = {3.f/95.f, 7.f/95.f, 10.f/95.f, 10.f/95.f, 10.f/95.f,
                                     10.f/95.f, 10.f/95.f, 10.f/95.f, 25.f/95.f};
                float tailE = 0.f, farE = 0.f, c = 0.f, emdE = 0.f;
                #pragma unroll
                for (int k = 0; k < K; ++k) {
                    const float twk = t2[2 * k];
                    const float ttk = t2[2 * k + 1];
                    tailE = fmaf(twk, e[k], tailE);
                    if (twk > 0.f) farE = fmaxf(farE, e[k]);
                    c += e[k];
                    const float v = fmaf(ttk, -s, c);   // c - t*s
                    emdE = fmaf(v * v, cw[k], emdE);
                }

                const float rAf = fmaxf(fmaf(DELTA_FAR,   s, farE - eyE), 0.f);
                const float nmx = fmaxf(elE, erE);
                const float rAl = fmaxf(fmaf(PROB_MARGIN, s, nmx - eyE), 0.f);

                float ord = fmaf(W_FAR, rAf, W_TAIL * tailE);
                ord = fmaf(W_LPEAK, rAl, ord);
                ord = fmaf(W_EMD * emdE, inv, ord);     // emd carries inv^2 total
                acc += fmaf(nll, INV_LOGK, (ALPHA * inv) * ord);
            }
        }
        __syncwarp();          // lanes done before next stage overwrites buffer
        cur ^= 1;
    }

    // deterministic block reduction
    #pragma unroll
    for (int o = 16; o > 0; o >>= 1)
        acc += __shfl_down_sync(0xffffffffu, acc, o);
    if (lane == 0) wsum[wid] = acc;
    __syncthreads();
    if (threadIdx.x == 0) {
        float b = 0.f;
        #pragma unroll
        for (int w = 0; w < WARPS; ++w) b += wsum[w];
        g_partials[blockIdx.x] = (double)b;
        __threadfence();
        const unsigned old = atomicAdd(&g_count, 1u);
        s_last = (old == GRID - 1) ? 1 : 0;
    }
    __syncthreads();

    // last block performs the deterministic, fixed-order final sum
    if (s_last) {
        __shared__ double dsum[WARPS];
        double sd = 0.0;
        #pragma unroll
        for (int i = 0; i < GRID / TPB; ++i)
            sd += g_partials[threadIdx.x + i * TPB];
        #pragma unroll
        for (int o = 16; o > 0; o >>= 1)
            sd += __shfl_down_sync(0xffffffffu, sd, o);
        if (lane == 0) dsum[wid] = sd;
        __syncthreads();
        if (threadIdx.x == 0) {
            double t = 0.0;
            #pragma unroll
            for (int w = 0; w < WARPS; ++w) t += dsum[w];
            out[0] = (float)(t * inv_n);
            g_count = 0;   // reset for next graph replay
        }
    }
}

extern "C" void kernel_launch(void* const* d_in, const int* in_sizes, int n_in,
                              void* d_out, int out_size)
{
    const float* logits = (const float*)d_in[0];
    const int*   yv     = (const int*)d_in[1];
    const int n = (n_in >= 2) ? in_sizes[1] : in_sizes[0] / K;

    ordinal_loss_fused<<<GRID, TPB>>>(logits, yv, (float*)d_out,
                                      n, 1.0 / (double)n);
}